// round 11
// baseline (speedup 1.0000x reference)
#include <cuda_runtime.h>
#include <cstdint>

// Problem constants
#define B_   4
#define S_   2048
#define D_   1024
#define H_   16
#define HD_  64
#define BH_  (B_ * H_)          // 64
#define NKT_ 16                 // key tiles (of 128) per row -> partial-sum slots

// Scratch (allocation-free rule: __device__ globals)
__device__ float g_Q[B_ * S_ * D_];
__device__ float g_K[B_ * S_ * D_];
__device__ float g_V[B_ * S_ * D_];
__device__ float g_X[B_ * S_ * D_];
__device__ float g_rsp[(size_t)BH_ * S_ * NKT_];   // per-(row, ktile) partial exp sums

// ---------------------------------------------------------------------------
// C[m,n] = sum_k A[m,k] * W[n,k] + bias[n]     (M=8192, N=1024, K=1024)
// 128x128 tile, BK=8, 8x8 per thread, 256 threads.
// ---------------------------------------------------------------------------
__global__ __launch_bounds__(256)
void gemm_abt_kernel(const float* __restrict__ A, const float* __restrict__ W,
                     const float* __restrict__ bias, float* __restrict__ C)
{
    constexpr int N = 1024, K = 1024;
    __shared__ float As[8][128];
    __shared__ float Bs[8][128];

    const int tid = threadIdx.x;
    const int m0  = blockIdx.y * 128;
    const int n0  = blockIdx.x * 128;
    const int lr  = tid >> 1;            // 0..127
    const int lc  = (tid & 1) << 2;      // 0 or 4
    const int tx  = tid & 15;            // n sub-tile
    const int ty  = tid >> 4;            // m sub-tile

    const float* Ap = A + (size_t)(m0 + lr) * K + lc;
    const float* Wp = W + (size_t)(n0 + lr) * K + lc;

    float acc[8][8] = {};

    for (int kt = 0; kt < K; kt += 8) {
        float4 a4 = *reinterpret_cast<const float4*>(Ap + kt);
        float4 b4 = *reinterpret_cast<const float4*>(Wp + kt);
        As[lc + 0][lr] = a4.x; As[lc + 1][lr] = a4.y;
        As[lc + 2][lr] = a4.z; As[lc + 3][lr] = a4.w;
        Bs[lc + 0][lr] = b4.x; Bs[lc + 1][lr] = b4.y;
        Bs[lc + 2][lr] = b4.z; Bs[lc + 3][lr] = b4.w;
        __syncthreads();

        #pragma unroll
        for (int k = 0; k < 8; k++) {
            float ra[8], rb[8];
            #pragma unroll
            for (int i = 0; i < 8; i++) ra[i] = As[k][ty * 8 + i];
            #pragma unroll
            for (int j = 0; j < 8; j++) rb[j] = Bs[k][tx * 8 + j];
            #pragma unroll
            for (int i = 0; i < 8; i++) {
                #pragma unroll
                for (int j = 0; j < 8; j++) {
                    acc[i][j] = fmaf(ra[i], rb[j], acc[i][j]);
                }
            }
        }
        __syncthreads();
    }

    float bb[8];
    #pragma unroll
    for (int j = 0; j < 8; j++) bb[j] = bias[n0 + tx * 8 + j];

    #pragma unroll
    for (int i = 0; i < 8; i++) {
        float* Cp = C + (size_t)(m0 + ty * 8 + i) * N + n0 + tx * 8;
        float4 v0 = make_float4(acc[i][0] + bb[0], acc[i][1] + bb[1],
                                acc[i][2] + bb[2], acc[i][3] + bb[3]);
        float4 v1 = make_float4(acc[i][4] + bb[4], acc[i][5] + bb[5],
                                acc[i][6] + bb[6], acc[i][7] + bb[7]);
        *reinterpret_cast<float4*>(Cp)     = v0;
        *reinterpret_cast<float4*>(Cp + 4) = v1;
    }
}

// ---------------------------------------------------------------------------
// Scores: P[bh, q, k] = exp(mask ? q·k / 8 : -inf)  (unnormalized),
// plus per-(row, ktile) partial exp sums (deterministic, no atomics).
// One block = one (bh, 128q x 128k) tile. grid = (16, 16, 64).
// No max-subtraction: logits are bounded (|l| <~ 20), exp(-1e10) -> 0 matches mask.
// ---------------------------------------------------------------------------
__global__ __launch_bounds__(256)
void scores_kernel(const float* __restrict__ Q, const float* __restrict__ Kmat,
                   const int* __restrict__ mask, float* __restrict__ P,
                   float* __restrict__ rsp)
{
    __shared__ float As[8][128];
    __shared__ float Bs[8][128];
    __shared__ float red[128][17];   // padded to avoid bank conflicts

    const int tid = threadIdx.x;
    const int bh  = blockIdx.z;
    const int b   = bh >> 4;
    const int h   = bh & 15;
    const int q0  = blockIdx.y * 128;
    const int k0  = blockIdx.x * 128;
    const int lr  = tid >> 1;
    const int lc  = (tid & 1) << 2;
    const int tx  = tid & 15;
    const int ty  = tid >> 4;

    const float* Qp = Q    + (size_t)(b * S_ + q0 + lr) * D_ + h * HD_ + lc;
    const float* Kp = Kmat + (size_t)(b * S_ + k0 + lr) * D_ + h * HD_ + lc;

    float acc[8][8] = {};

    #pragma unroll
    for (int kt = 0; kt < HD_; kt += 8) {
        float4 a4 = *reinterpret_cast<const float4*>(Qp + kt);
        float4 b4 = *reinterpret_cast<const float4*>(Kp + kt);
        As[lc + 0][lr] = a4.x; As[lc + 1][lr] = a4.y;
        As[lc + 2][lr] = a4.z; As[lc + 3][lr] = a4.w;
        Bs[lc + 0][lr] = b4.x; Bs[lc + 1][lr] = b4.y;
        Bs[lc + 2][lr] = b4.z; Bs[lc + 3][lr] = b4.w;
        __syncthreads();

        #pragma unroll
        for (int k = 0; k < 8; k++) {
            float ra[8], rb[8];
            #pragma unroll
            for (int i = 0; i < 8; i++) ra[i] = As[k][ty * 8 + i];
            #pragma unroll
            for (int j = 0; j < 8; j++) rb[j] = Bs[k][tx * 8 + j];
            #pragma unroll
            for (int i = 0; i < 8; i++) {
                #pragma unroll
                for (int j = 0; j < 8; j++) {
                    acc[i][j] = fmaf(ra[i], rb[j], acc[i][j]);
                }
            }
        }
        __syncthreads();
    }

    // mask + exp + partial row sums
    int km[8];
    #pragma unroll
    for (int j = 0; j < 8; j++) km[j] = mask[b * S_ + k0 + tx * 8 + j];

    #pragma unroll
    for (int i = 0; i < 8; i++) {
        float s = 0.f;
        #pragma unroll
        for (int j = 0; j < 8; j++) {
            float v = km[j] ? __expf(acc[i][j] * 0.125f) : 0.f;
            acc[i][j] = v;
            s += v;
        }
        red[ty * 8 + i][tx] = s;
    }

    // store unnormalized P (normalized in-place by av_kernel)
    float* Pb = P + (size_t)bh * S_ * S_;
    #pragma unroll
    for (int i = 0; i < 8; i++) {
        float* pp = Pb + (size_t)(q0 + ty * 8 + i) * S_ + k0 + tx * 8;
        float4 v0 = make_float4(acc[i][0], acc[i][1], acc[i][2], acc[i][3]);
        float4 v1 = make_float4(acc[i][4], acc[i][5], acc[i][6], acc[i][7]);
        *reinterpret_cast<float4*>(pp)     = v0;
        *reinterpret_cast<float4*>(pp + 4) = v1;
    }

    __syncthreads();
    if (tid < 128) {
        float s = 0.f;
        #pragma unroll
        for (int t = 0; t < 16; t++) s += red[tid][t];
        rsp[((size_t)bh * S_ + q0 + tid) * NKT_ + blockIdx.x] = s;
    }
}

// ---------------------------------------------------------------------------
// AV: X = (P / rowsum) @ V, per (bh, 256q-row tile). Also rewrites P in-place
// as the normalized attention (each element read/written exactly once).
// grid = (8, 64). 256q x 64hd tile, BK=16, 8x8 per thread.
// ---------------------------------------------------------------------------
__global__ __launch_bounds__(256)
void av_kernel(float* __restrict__ P, const float* __restrict__ V,
               const float* __restrict__ rsp, float* __restrict__ X)
{
    __shared__ float As[16][256];
    __shared__ float Bs[16][64];
    __shared__ float invs[256];

    const int tid = threadIdx.x;
    const int bh  = blockIdx.y;
    const int b   = bh >> 4;
    const int h   = bh & 15;
    const int q0  = blockIdx.x * 256;

    {
        const float* rp = rsp + ((size_t)bh * S_ + q0 + tid) * NKT_;
        float s = 0.f;
        #pragma unroll
        for (int t = 0; t < 16; t++) s += rp[t];
        invs[tid] = 1.0f / s;
    }
    __syncthreads();

    const int tx   = tid & 7;          // 8 col groups * 8 = 64 cols
    const int ty   = tid >> 3;         // 32 row groups * 8 = 256 rows
    const int pcol = (tid & 3) << 2;   // 0,4,8,12
    const int prow = tid >> 2;         // 0..63
    const int vrow = tid >> 4;         // 0..15
    const int vcol = (tid & 15) << 2;  // 0..60

    float acc[8][8] = {};
    float* Pb       = P + (size_t)bh * S_ * S_;
    const float* Vb = V + (size_t)b * S_ * D_ + h * HD_;

    for (int kt = 0; kt < S_; kt += 16) {
        #pragma unroll
        for (int rr = 0; rr < 4; rr++) {
            const int row = prow + rr * 64;
            const float inv = invs[row];
            float* pp = Pb + (size_t)(q0 + row) * S_ + kt + pcol;
            float4 p4 = *reinterpret_cast<const float4*>(pp);
            p4.x *= inv; p4.y *= inv; p4.z *= inv; p4.w *= inv;
            As[pcol + 0][row] = p4.x; As[pcol + 1][row] = p4.y;
            As[pcol + 2][row] = p4.z; As[pcol + 3][row] = p4.w;
            *reinterpret_cast<float4*>(pp) = p4;   // normalized attention out
        }
        {
            const float4 v4 = *reinterpret_cast<const float4*>(
                Vb + (size_t)(kt + vrow) * D_ + vcol);
            *reinterpret_cast<float4*>(&Bs[vrow][vcol]) = v4;
        }
        __syncthreads();

        #pragma unroll
        for (int k = 0; k < 16; k++) {
            float ra[8], rb[8];
            #pragma unroll
            for (int i = 0; i < 8; i++) ra[i] = As[k][ty * 8 + i];
            #pragma unroll
            for (int j = 0; j < 8; j++) rb[j] = Bs[k][tx * 8 + j];
            #pragma unroll
            for (int i = 0; i < 8; i++) {
                #pragma unroll
                for (int j = 0; j < 8; j++) {
                    acc[i][j] = fmaf(ra[i], rb[j], acc[i][j]);
                }
            }
        }
        __syncthreads();
    }

    // X in [B, S, D] layout so the output projection consumes it directly
    #pragma unroll
    for (int i = 0; i < 8; i++) {
        float* xp = X + (size_t)(b * S_ + q0 + ty * 8 + i) * D_ + h * HD_ + tx * 8;
        float4 v0 = make_float4(acc[i][0], acc[i][1], acc[i][2], acc[i][3]);
        float4 v1 = make_float4(acc[i][4], acc[i][5], acc[i][6], acc[i][7]);
        *reinterpret_cast<float4*>(xp)     = v0;
        *reinterpret_cast<float4*>(xp + 4) = v1;
    }
}

// ---------------------------------------------------------------------------
extern "C" void kernel_launch(void* const* d_in, const int* in_sizes, int n_in,
                              void* d_out, int out_size)
{
    (void)in_sizes; (void)n_in; (void)out_size;

    const float* query = (const float*)d_in[0];
    const float* key_  = (const float*)d_in[1];
    const float* value = (const float*)d_in[2];
    const int*   mask  = (const int*)d_in[3];
    const float* Wq    = (const float*)d_in[4];
    const float* bq    = (const float*)d_in[5];
    const float* Wk    = (const float*)d_in[6];
    const float* bk    = (const float*)d_in[7];
    const float* Wv    = (const float*)d_in[8];
    const float* bv    = (const float*)d_in[9];
    const float* Wo    = (const float*)d_in[10];
    const float* bo    = (const float*)d_in[11];

    float* xout = (float*)d_out;                              // [B,S,D]
    float* pout = xout + (size_t)B_ * S_ * D_;                // [B,H,S,S]

    void *pQ, *pK, *pV, *pX, *pR;
    cudaGetSymbolAddress(&pQ, g_Q);
    cudaGetSymbolAddress(&pK, g_K);
    cudaGetSymbolAddress(&pV, g_V);
    cudaGetSymbolAddress(&pX, g_X);
    cudaGetSymbolAddress(&pR, g_rsp);

    const dim3 gproj(1024 / 128, 8192 / 128);   // (8, 64)

    gemm_abt_kernel<<<gproj, 256>>>(query, Wq, bq, (float*)pQ);
    gemm_abt_kernel<<<gproj, 256>>>(key_,  Wk, bk, (float*)pK);
    gemm_abt_kernel<<<gproj, 256>>>(value, Wv, bv, (float*)pV);

    scores_kernel<<<dim3(S_ / 128, S_ / 128, BH_), 256>>>(
        (const float*)pQ, (const float*)pK, mask, pout, (float*)pR);

    av_kernel<<<dim3(S_ / 256, BH_), 256>>>(
        pout, (const float*)pV, (const float*)pR, (float*)pX);

    gemm_abt_kernel<<<gproj, 256>>>((const float*)pX, Wo, bo, xout);
}